// round 8
// baseline (speedup 1.0000x reference)
#include <cuda_runtime.h>
#include <cuda_bf16.h>

#define LAT     32
#define HID     128
#define GSZ     512     // 4*HID
#define NVAR    9
#define NSCEN   4
#define IH0_W   (NVAR + HID)   // 137
#define INIT_W  (LAT + HID)    // 160

#define M       32      // batch rows per CTA
#define THREADS 256
#define TM      8       // rows per thread
#define TJ      2       // hidden units per thread (one f32x2 pair)
#define CG      (HID / TJ)     // 64 column-groups

typedef unsigned long long u64;

// -------- device scratch: weights relaid out [k][q][cg][4] --------
// per k-row (512 floats): q = gate-pair (0: gates0,1 ; 1: gates2,3)
//   float idx = k*512 + q*256 + cg*4 + g'*2 + jj   (g' = g&1)
// A warp (32 consecutive cg) thus reads a CONTIGUOUS 512B span per LDG.128.
__device__ __align__(16) float g_Wt0[HID * GSZ];        // W_hh0
__device__ __align__(16) float g_Wt1[2 * HID * GSZ];    // k<128: W_ih1, k>=128: W_hh1

__global__ void transpose_kernel(const float* __restrict__ W_hh0,
                                 const float* __restrict__ W_ih1,
                                 const float* __restrict__ W_hh1) {
    int i = blockIdx.x * blockDim.x + threadIdx.x;   // i = k*512 + col
    if (i >= HID * GSZ) return;
    int k = i >> 9, col = i & (GSZ - 1);
    int g = col >> 7, w = col & 127;
    int cg = w >> 1, jj = w & 1;
    int dst = (k << 9) + ((g >> 1) << 8) + (cg << 2) + ((g & 1) << 1) + jj;
    g_Wt0[dst]             = W_hh0[col * HID + k];
    g_Wt1[dst]             = W_ih1[col * HID + k];
    g_Wt1[HID * GSZ + dst] = W_hh1[col * HID + k];
}

__device__ __forceinline__ float sigf(float x) {
    return __fdividef(1.0f, 1.0f + __expf(-x));
}
__device__ __forceinline__ float tanh_fast(float x) {
    return __fdividef(2.0f, 1.0f + __expf(-2.0f * x)) - 1.0f;
}

// ---- packed fp32x2 helpers (sm_103a FFMA2 path) ----
__device__ __forceinline__ u64 pack2(float lo, float hi) {
    u64 d;
    asm("mov.b64 %0, {%1, %2};" : "=l"(d) : "f"(lo), "f"(hi));
    return d;
}
__device__ __forceinline__ void unpack2(u64 v, float& lo, float& hi) {
    asm("mov.b64 {%0, %1}, %2;" : "=f"(lo), "=f"(hi) : "l"(v));
}
__device__ __forceinline__ u64 ffma2(u64 a, u64 b, u64 c) {
    u64 d;
    asm("fma.rn.f32x2 %0, %1, %2, %3;" : "=l"(d) : "l"(a), "l"(b), "l"(c));
    return d;
}

// acc[g][r] (+)= shH[m][k] * W[k][col-pair cg], K = 128, packed pairs.
// Per 4-k block: hoist 8 h-LDS.128; per 2-k half: issue 4 weight LDG.128
// ahead of 64 ffma2 (MLP ~4-6 to hide L2 latency on weight misses).
__device__ __forceinline__ void gemm128_2(u64 acc[4][TM],
                                          const float* __restrict__ Wt,
                                          const float* __restrict__ shH,
                                          int ml0, int cg) {
    const float* wbase = Wt + (cg << 2);
    for (int k = 0; k < HID; k += 4) {
        float4 h[TM];
#pragma unroll
        for (int r = 0; r < TM; ++r)
            h[r] = *(const float4*)(shH + (ml0 + r) * HID + k);
#pragma unroll
        for (int kh = 0; kh < 4; kh += 2) {
            const float* w0p = wbase + ((k + kh) << 9);
            const float* w1p = wbase + ((k + kh + 1) << 9);
            longlong2 a0 = *(const longlong2*)(w0p);          // gates 0,1 @ kk
            longlong2 b0 = *(const longlong2*)(w0p + 256);    // gates 2,3 @ kk
            longlong2 a1 = *(const longlong2*)(w1p);          // gates 0,1 @ kk+1
            longlong2 b1 = *(const longlong2*)(w1p + 256);    // gates 2,3 @ kk+1
#pragma unroll
            for (int r = 0; r < TM; ++r) {
                float hv0 = (kh == 0) ? h[r].x : h[r].z;
                u64 h2 = pack2(hv0, hv0);
                acc[0][r] = ffma2(h2, (u64)a0.x, acc[0][r]);
                acc[1][r] = ffma2(h2, (u64)a0.y, acc[1][r]);
                acc[2][r] = ffma2(h2, (u64)b0.x, acc[2][r]);
                acc[3][r] = ffma2(h2, (u64)b0.y, acc[3][r]);
            }
#pragma unroll
            for (int r = 0; r < TM; ++r) {
                float hv1 = (kh == 0) ? h[r].y : h[r].w;
                u64 h2 = pack2(hv1, hv1);
                acc[0][r] = ffma2(h2, (u64)a1.x, acc[0][r]);
                acc[1][r] = ffma2(h2, (u64)a1.y, acc[1][r]);
                acc[2][r] = ffma2(h2, (u64)b1.x, acc[2][r]);
                acc[3][r] = ffma2(h2, (u64)b1.y, acc[3][r]);
            }
        }
    }
}

// SMEM layout (floats)
#define SM_H0    0
#define SM_H1    (SM_H0 + M * HID)
#define SM_C0    (SM_H1 + M * HID)
#define SM_C1    (SM_C0 + M * HID)
#define SM_PREV  (SM_C1 + M * HID)        // [M][12]
#define SM_P0    (SM_PREV + M * 12)       // [4][512]
#define SM_PRE1  (SM_P0 + NSCEN * GSZ)    // [512]
#define SM_WP    (SM_PRE1 + GSZ)          // [9][q][cg][4]; QI [4][512] overlaid (phase 1)
#define SM_WOUT  (SM_WP + NVAR * GSZ)     // [9][128]
#define SM_BOUT  (SM_WOUT + NVAR * HID)   // [16]
#define SM_SCEN  (SM_BOUT + 16)           // M ints
#define SM_FLAG  (SM_SCEN + M)
#define SM_FLOATS (SM_FLAG + 4)
#define SMEM_BYTES (SM_FLOATS * 4)

__global__ void __launch_bounds__(THREADS, 2)
lstm_kernel(const float* __restrict__ z, const int* __restrict__ scen_raw,
            const float* __restrict__ emb,
            const float* __restrict__ W_init, const float* __restrict__ b_init,
            const float* __restrict__ W_ih0,
            const float* __restrict__ b_ih0, const float* __restrict__ b_hh0,
            const float* __restrict__ b_ih1, const float* __restrict__ b_hh1,
            const float* __restrict__ W_out, const float* __restrict__ b_out,
            float* __restrict__ outp, int T) {
    extern __shared__ float sm[];
    float* sh_h0   = sm + SM_H0;
    float* sh_h1   = sm + SM_H1;
    float* sh_c0   = sm + SM_C0;
    float* sh_c1   = sm + SM_C1;
    float* sh_prev = sm + SM_PREV;
    float* sh_P0   = sm + SM_P0;
    float* sh_pre1 = sm + SM_PRE1;
    float* sh_Wp   = sm + SM_WP;      // phase 2
    float* sh_QI   = sm + SM_WP;      // phase 1 (overlay)
    float* sh_Wout = sm + SM_WOUT;
    float* sh_bout = sm + SM_BOUT;
    int*   sh_scen = (int*)(sm + SM_SCEN);
    int*   sh_flag = (int*)(sm + SM_FLAG);

    const int tid = threadIdx.x;
    const int m0  = blockIdx.x * M;

    // ---- scenario dtype detection (int64 vs int32): deterministic scan ----
    if (tid == 0) *sh_flag = 1;
    __syncthreads();
    {
        const unsigned* su = (const unsigned*)scen_raw;
        for (int k = tid; k < 512; k += THREADS)
            if (su[2 * k + 1] != 0u) *sh_flag = 0;
    }
    __syncthreads();
    const int is64 = *sh_flag;

    // ---- phase 0: tables into SMEM (QI overlaid on WP region) ----
    for (int m = tid; m < M; m += THREADS)
        sh_scen[m] = is64 ? scen_raw[2 * (m0 + m)] : scen_raw[m0 + m];
    for (int i = tid; i < NVAR * HID; i += THREADS) sh_Wout[i] = W_out[i];
    if (tid < NVAR) sh_bout[tid] = b_out[tid];
    for (int i = tid; i < GSZ; i += THREADS) sh_pre1[i] = b_ih1[i] + b_hh1[i];
    for (int i = tid; i < M * 12; i += THREADS) sh_prev[i] = 0.0f;
    for (int i = tid; i < NSCEN * GSZ; i += THREADS) {
        int s = i >> 9, j = i & (GSZ - 1);
        const float* e  = emb + s * HID;
        const float* w0 = W_ih0 + j * IH0_W + NVAR;
        const float* w1 = W_init + j * INIT_W + LAT;
        float v0 = b_ih0[j] + b_hh0[j];
        float v1 = b_init[j];
#pragma unroll 4
        for (int k = 0; k < HID; ++k) {
            float ek = e[k];
            v0 = fmaf(ek, w0[k], v0);
            v1 = fmaf(ek, w1[k], v1);
        }
        sh_P0[i] = v0;
        sh_QI[i] = v1;
    }
    __syncthreads();

    const int cg  = tid & (CG - 1);
    const int rg  = tid >> 6;
    const int j0  = cg * TJ;
    const int ml0 = rg * TM;

    // ---- phase 1: h_init = z @ Wz^T + QI[scenario]  (slots: h0,c0,h1,c1) ----
    {
        float acc[4][TM][TJ];
#pragma unroll
        for (int r = 0; r < TM; ++r) {
            int s = sh_scen[ml0 + r];
            const float* q = sh_QI + s * GSZ + j0;
#pragma unroll
            for (int g = 0; g < 4; ++g) {
                acc[g][r][0] = q[g * HID];
                acc[g][r][1] = q[g * HID + 1];
            }
        }
        for (int k = 0; k < LAT; k += 4) {
            float4 zr[TM];
#pragma unroll
            for (int r = 0; r < TM; ++r)
                zr[r] = *(const float4*)(z + (size_t)(m0 + ml0 + r) * LAT + k);
#pragma unroll
            for (int kk = 0; kk < 4; ++kk) {
                float w[4][TJ];
#pragma unroll
                for (int g = 0; g < 4; ++g)
#pragma unroll
                    for (int jj = 0; jj < TJ; ++jj)
                        w[g][jj] = W_init[(size_t)(g * HID + j0 + jj) * INIT_W + k + kk];
#pragma unroll
                for (int r = 0; r < TM; ++r) {
                    float hv = (kk == 0) ? zr[r].x : (kk == 1) ? zr[r].y
                             : (kk == 2) ? zr[r].z : zr[r].w;
#pragma unroll
                    for (int g = 0; g < 4; ++g) {
                        acc[g][r][0] = fmaf(hv, w[g][0], acc[g][r][0]);
                        acc[g][r][1] = fmaf(hv, w[g][1], acc[g][r][1]);
                    }
                }
            }
        }
#pragma unroll
        for (int r = 0; r < TM; ++r)
#pragma unroll
            for (int jj = 0; jj < TJ; ++jj) {
                int off = (ml0 + r) * HID + j0 + jj;
                sh_h0[off] = acc[0][r][jj];
                sh_c0[off] = acc[1][r][jj];
                sh_h1[off] = acc[2][r][jj];
                sh_c1[off] = acc[3][r][jj];
            }
    }
    __syncthreads();

    // ---- load WP (overwrites QI overlay): layout [v][q][cg][4] ----
    for (int i = tid; i < NVAR * GSZ; i += THREADS) {
        int v = i / GSZ, rem = i - v * GSZ;
        int q = rem >> 8, c = (rem >> 2) & 63, t = rem & 3;
        int g = q * 2 + (t >> 1), jj = t & 1;
        sh_Wp[i] = W_ih0[(g * HID + c * 2 + jj) * IH0_W + v];
    }
    __syncthreads();

    // ---- phase 2: time loop ----
    for (int t = 0; t < T; ++t) {
        u64 acc[4][TM];

        // layer0 gates: init from P0[scenario], add prev (K=9), add h0@W_hh0^T
#pragma unroll
        for (int r = 0; r < TM; ++r) {
            int s = sh_scen[ml0 + r];
            const float* p = sh_P0 + s * GSZ + j0;
#pragma unroll
            for (int g = 0; g < 4; ++g)
                acc[g][r] = *(const u64*)(p + g * HID);
        }
#pragma unroll
        for (int v = 0; v < NVAR; ++v) {
            const float* wr = sh_Wp + (v << 9) + (cg << 2);
            longlong2 qa = *(const longlong2*)(wr);
            longlong2 qb = *(const longlong2*)(wr + 256);
            u64 w0 = (u64)qa.x, w1 = (u64)qa.y;
            u64 w2 = (u64)qb.x, w3 = (u64)qb.y;
#pragma unroll
            for (int r = 0; r < TM; ++r) {
                float pv = sh_prev[(ml0 + r) * 12 + v];
                u64 p2 = pack2(pv, pv);
                acc[0][r] = ffma2(p2, w0, acc[0][r]);
                acc[1][r] = ffma2(p2, w1, acc[1][r]);
                acc[2][r] = ffma2(p2, w2, acc[2][r]);
                acc[3][r] = ffma2(p2, w3, acc[3][r]);
            }
        }
        gemm128_2(acc, g_Wt0, sh_h0, ml0, cg);
        __syncthreads();                              // S1: done reading sh_h0

        // cell 0
#pragma unroll
        for (int r = 0; r < TM; ++r) {
            float i0, i1, f0, f1, g0, g1, o0, o1;
            unpack2(acc[0][r], i0, i1);
            unpack2(acc[1][r], f0, f1);
            unpack2(acc[2][r], g0, g1);
            unpack2(acc[3][r], o0, o1);
            int off = (ml0 + r) * HID + j0;
            float c0n = sigf(f0) * sh_c0[off]     + sigf(i0) * tanh_fast(g0);
            float c1n = sigf(f1) * sh_c0[off + 1] + sigf(i1) * tanh_fast(g1);
            sh_c0[off]     = c0n;
            sh_c0[off + 1] = c1n;
            sh_h0[off]     = sigf(o0) * tanh_fast(c0n);
            sh_h0[off + 1] = sigf(o1) * tanh_fast(c1n);
        }
        __syncthreads();                              // S2: h0n visible

        // layer1 gates: pre1 + h0n@W_ih1^T + h1@W_hh1^T
#pragma unroll
        for (int r = 0; r < TM; ++r)
#pragma unroll
            for (int g = 0; g < 4; ++g)
                acc[g][r] = *(const u64*)(sh_pre1 + g * HID + j0);
        gemm128_2(acc, g_Wt1, sh_h0, ml0, cg);
        gemm128_2(acc, g_Wt1 + HID * GSZ, sh_h1, ml0, cg);
        __syncthreads();                              // S3: done reading sh_h1

        // cell 1
#pragma unroll
        for (int r = 0; r < TM; ++r) {
            float i0, i1, f0, f1, g0, g1, o0, o1;
            unpack2(acc[0][r], i0, i1);
            unpack2(acc[1][r], f0, f1);
            unpack2(acc[2][r], g0, g1);
            unpack2(acc[3][r], o0, o1);
            int off = (ml0 + r) * HID + j0;
            float c0n = sigf(f0) * sh_c1[off]     + sigf(i0) * tanh_fast(g0);
            float c1n = sigf(f1) * sh_c1[off + 1] + sigf(i1) * tanh_fast(g1);
            sh_c1[off]     = c0n;
            sh_c1[off + 1] = c1n;
            sh_h1[off]     = sigf(o0) * tanh_fast(c0n);
            sh_h1[off + 1] = sigf(o1) * tanh_fast(c1n);
        }
        __syncthreads();                              // S4: h1n visible

        // output head: out = h1n @ W_out^T + b_out ; also becomes prev
        for (int idx = tid; idx < M * NVAR; idx += THREADS) {
            int m = idx / NVAR, v = idx - m * NVAR;
            const float* hrow = sh_h1 + m * HID;
            const float* wrow = sh_Wout + v * HID;
            float s = sh_bout[v];
#pragma unroll 4
            for (int k = 0; k < HID; k += 4) {
                s = fmaf(hrow[k],     wrow[k],     s);
                s = fmaf(hrow[k + 1], wrow[k + 1], s);
                s = fmaf(hrow[k + 2], wrow[k + 2], s);
                s = fmaf(hrow[k + 3], wrow[k + 3], s);
            }
            sh_prev[m * 12 + v] = s;
            outp[((size_t)(m0 + m) * T + t) * NVAR + v] = s;
        }
        __syncthreads();                              // S5: prev visible
    }
}

extern "C" void kernel_launch(void* const* d_in, const int* in_sizes, int n_in,
                              void* d_out, int out_size) {
    // input order: z, scenario, [seq_length], emb, W_init, b_init, W_ih0, W_hh0,
    //              b_ih0, b_hh0, W_ih1, W_hh1, b_ih1, b_hh1, W_out, b_out
    int off = (n_in >= 16) ? 1 : 0;   // seq_length scalar present or not
    const float* z      = (const float*)d_in[0];
    const int*   scen   = (const int*)d_in[1];
    const float* emb    = (const float*)d_in[2 + off];
    const float* W_init = (const float*)d_in[3 + off];
    const float* b_init = (const float*)d_in[4 + off];
    const float* W_ih0  = (const float*)d_in[5 + off];
    const float* W_hh0  = (const float*)d_in[6 + off];
    const float* b_ih0  = (const float*)d_in[7 + off];
    const float* b_hh0  = (const float*)d_in[8 + off];
    const float* W_ih1  = (const float*)d_in[9 + off];
    const float* W_hh1  = (const float*)d_in[10 + off];
    const float* b_ih1  = (const float*)d_in[11 + off];
    const float* b_hh1  = (const float*)d_in[12 + off];
    const float* W_out  = (const float*)d_in[13 + off];
    const float* b_out  = (const float*)d_in[14 + off];
    float* outp = (float*)d_out;

    int B = in_sizes[0] / LAT;
    int T = out_size / (B * NVAR);

    cudaFuncSetAttribute(lstm_kernel,
                         cudaFuncAttributeMaxDynamicSharedMemorySize, SMEM_BYTES);

    transpose_kernel<<<(HID * GSZ + 255) / 256, 256>>>(W_hh0, W_ih1, W_hh1);
    lstm_kernel<<<B / M, THREADS, SMEM_BYTES>>>(
        z, scen, emb, W_init, b_init, W_ih0,
        b_ih0, b_hh0, b_ih1, b_hh1, W_out, b_out, outp, T);
}

// round 9
// speedup vs baseline: 1.0007x; 1.0007x over previous
#include <cuda_runtime.h>
#include <cuda_bf16.h>

#define LAT     32
#define HID     128
#define GSZ     512     // 4*HID
#define NVAR    9
#define NSCEN   4
#define IH0_W   (NVAR + HID)   // 137
#define INIT_W  (LAT + HID)    // 160

#define M       32      // batch rows per CTA
#define THREADS 256
#define TM      8       // rows per thread
#define TJ      2       // hidden units per thread (one f32x2 pair)
#define CG      (HID / TJ)     // 64 column-groups

typedef unsigned long long u64;

// -------- device scratch: weights relaid out [k][q][cg][4] --------
// per k-row (512 floats): q = gate-pair (0: gates0,1 ; 1: gates2,3)
//   float idx = k*512 + q*256 + cg*4 + g'*2 + jj   (g' = g&1)
// A warp (32 consecutive cg) reads a CONTIGUOUS 512B span per LDG.128.
__device__ __align__(16) float g_Wt0[HID * GSZ];        // W_hh0
__device__ __align__(16) float g_Wt1[2 * HID * GSZ];    // k<128: W_ih1, k>=128: W_hh1

__global__ void transpose_kernel(const float* __restrict__ W_hh0,
                                 const float* __restrict__ W_ih1,
                                 const float* __restrict__ W_hh1) {
    int i = blockIdx.x * blockDim.x + threadIdx.x;   // i = k*512 + col
    if (i >= HID * GSZ) return;
    int k = i >> 9, col = i & (GSZ - 1);
    int g = col >> 7, w = col & 127;
    int cg = w >> 1, jj = w & 1;
    int dst = (k << 9) + ((g >> 1) << 8) + (cg << 2) + ((g & 1) << 1) + jj;
    g_Wt0[dst]             = W_hh0[col * HID + k];
    g_Wt1[dst]             = W_ih1[col * HID + k];
    g_Wt1[HID * GSZ + dst] = W_hh1[col * HID + k];
}

__device__ __forceinline__ float sigf(float x) {
    return __fdividef(1.0f, 1.0f + __expf(-x));
}
__device__ __forceinline__ float tanh_fast(float x) {
    return __fdividef(2.0f, 1.0f + __expf(-2.0f * x)) - 1.0f;
}

// row-group-local barrier: 2 warps (64 threads), named barrier 1..4
__device__ __forceinline__ void rg_bar(int id) {
    asm volatile("bar.sync %0, 64;" :: "r"(id) : "memory");
}

// ---- packed fp32x2 helpers (sm_103a FFMA2 path) ----
__device__ __forceinline__ u64 pack2(float lo, float hi) {
    u64 d;
    asm("mov.b64 %0, {%1, %2};" : "=l"(d) : "f"(lo), "f"(hi));
    return d;
}
__device__ __forceinline__ void unpack2(u64 v, float& lo, float& hi) {
    asm("mov.b64 {%0, %1}, %2;" : "=f"(lo), "=f"(hi) : "l"(v));
}
__device__ __forceinline__ u64 ffma2(u64 a, u64 b, u64 c) {
    u64 d;
    asm("fma.rn.f32x2 %0, %1, %2, %3;" : "=l"(d) : "l"(a), "l"(b), "l"(c));
    return d;
}

// acc[g][r] (+)= shH[m][k] * W[k][col-pair cg], K = 128, packed pairs.
__device__ __forceinline__ void gemm128_2(u64 acc[4][TM],
                                          const float* __restrict__ Wt,
                                          const float* __restrict__ shH,
                                          int ml0, int cg) {
    const float* wbase = Wt + (cg << 2);
    for (int k = 0; k < HID; k += 4) {
        float4 h[TM];
#pragma unroll
        for (int r = 0; r < TM; ++r)
            h[r] = *(const float4*)(shH + (ml0 + r) * HID + k);
#pragma unroll
        for (int kh = 0; kh < 4; kh += 2) {
            const float* w0p = wbase + ((k + kh) << 9);
            const float* w1p = wbase + ((k + kh + 1) << 9);
            longlong2 a0 = *(const longlong2*)(w0p);          // gates 0,1 @ kk
            longlong2 b0 = *(const longlong2*)(w0p + 256);    // gates 2,3 @ kk
            longlong2 a1 = *(const longlong2*)(w1p);          // gates 0,1 @ kk+1
            longlong2 b1 = *(const longlong2*)(w1p + 256);    // gates 2,3 @ kk+1
#pragma unroll
            for (int r = 0; r < TM; ++r) {
                float hv0 = (kh == 0) ? h[r].x : h[r].z;
                u64 h2 = pack2(hv0, hv0);
                acc[0][r] = ffma2(h2, (u64)a0.x, acc[0][r]);
                acc[1][r] = ffma2(h2, (u64)a0.y, acc[1][r]);
                acc[2][r] = ffma2(h2, (u64)b0.x, acc[2][r]);
                acc[3][r] = ffma2(h2, (u64)b0.y, acc[3][r]);
            }
#pragma unroll
            for (int r = 0; r < TM; ++r) {
                float hv1 = (kh == 0) ? h[r].y : h[r].w;
                u64 h2 = pack2(hv1, hv1);
                acc[0][r] = ffma2(h2, (u64)a1.x, acc[0][r]);
                acc[1][r] = ffma2(h2, (u64)a1.y, acc[1][r]);
                acc[2][r] = ffma2(h2, (u64)b1.x, acc[2][r]);
                acc[3][r] = ffma2(h2, (u64)b1.y, acc[3][r]);
            }
        }
    }
}

// SMEM layout (floats)
#define SM_H0    0
#define SM_H1    (SM_H0 + M * HID)
#define SM_C0    (SM_H1 + M * HID)
#define SM_C1    (SM_C0 + M * HID)
#define SM_PREV  (SM_C1 + M * HID)        // [M][12]
#define SM_P0    (SM_PREV + M * 12)       // [4][512]
#define SM_PRE1  (SM_P0 + NSCEN * GSZ)    // [512]
#define SM_WP    (SM_PRE1 + GSZ)          // [9][q][cg][4]; QI [4][512] overlaid (phase 1)
#define SM_WOUT  (SM_WP + NVAR * GSZ)     // [9][128]
#define SM_BOUT  (SM_WOUT + NVAR * HID)   // [16]
#define SM_SCEN  (SM_BOUT + 16)           // M ints
#define SM_FLAG  (SM_SCEN + M)
#define SM_FLOATS (SM_FLAG + 4)
#define SMEM_BYTES (SM_FLOATS * 4)

__global__ void __launch_bounds__(THREADS, 2)
lstm_kernel(const float* __restrict__ z, const int* __restrict__ scen_raw,
            const float* __restrict__ emb,
            const float* __restrict__ W_init, const float* __restrict__ b_init,
            const float* __restrict__ W_ih0,
            const float* __restrict__ b_ih0, const float* __restrict__ b_hh0,
            const float* __restrict__ b_ih1, const float* __restrict__ b_hh1,
            const float* __restrict__ W_out, const float* __restrict__ b_out,
            float* __restrict__ outp, int T) {
    extern __shared__ float sm[];
    float* sh_h0   = sm + SM_H0;
    float* sh_h1   = sm + SM_H1;
    float* sh_c0   = sm + SM_C0;
    float* sh_c1   = sm + SM_C1;
    float* sh_prev = sm + SM_PREV;
    float* sh_P0   = sm + SM_P0;
    float* sh_pre1 = sm + SM_PRE1;
    float* sh_Wp   = sm + SM_WP;      // phase 2
    float* sh_QI   = sm + SM_WP;      // phase 1 (overlay)
    float* sh_Wout = sm + SM_WOUT;
    float* sh_bout = sm + SM_BOUT;
    int*   sh_scen = (int*)(sm + SM_SCEN);
    int*   sh_flag = (int*)(sm + SM_FLAG);

    const int tid = threadIdx.x;
    const int m0  = blockIdx.x * M;

    // ---- scenario dtype detection (int64 vs int32): deterministic scan ----
    if (tid == 0) *sh_flag = 1;
    __syncthreads();
    {
        const unsigned* su = (const unsigned*)scen_raw;
        for (int k = tid; k < 512; k += THREADS)
            if (su[2 * k + 1] != 0u) *sh_flag = 0;
    }
    __syncthreads();
    const int is64 = *sh_flag;

    // ---- phase 0: tables into SMEM (QI overlaid on WP region) ----
    for (int m = tid; m < M; m += THREADS)
        sh_scen[m] = is64 ? scen_raw[2 * (m0 + m)] : scen_raw[m0 + m];
    for (int i = tid; i < NVAR * HID; i += THREADS) sh_Wout[i] = W_out[i];
    if (tid < NVAR) sh_bout[tid] = b_out[tid];
    for (int i = tid; i < GSZ; i += THREADS) sh_pre1[i] = b_ih1[i] + b_hh1[i];
    for (int i = tid; i < M * 12; i += THREADS) sh_prev[i] = 0.0f;
    for (int i = tid; i < NSCEN * GSZ; i += THREADS) {
        int s = i >> 9, j = i & (GSZ - 1);
        const float* e  = emb + s * HID;
        const float* w0 = W_ih0 + j * IH0_W + NVAR;
        const float* w1 = W_init + j * INIT_W + LAT;
        float v0 = b_ih0[j] + b_hh0[j];
        float v1 = b_init[j];
#pragma unroll 4
        for (int k = 0; k < HID; ++k) {
            float ek = e[k];
            v0 = fmaf(ek, w0[k], v0);
            v1 = fmaf(ek, w1[k], v1);
        }
        sh_P0[i] = v0;
        sh_QI[i] = v1;
    }
    __syncthreads();

    const int cg  = tid & (CG - 1);
    const int rg  = tid >> 6;
    const int j0  = cg * TJ;
    const int ml0 = rg * TM;
    const int bid = rg + 1;          // named barrier id for this row-group

    // ---- phase 1: h_init = z @ Wz^T + QI[scenario]  (slots: h0,c0,h1,c1) ----
    {
        float acc[4][TM][TJ];
#pragma unroll
        for (int r = 0; r < TM; ++r) {
            int s = sh_scen[ml0 + r];
            const float* q = sh_QI + s * GSZ + j0;
#pragma unroll
            for (int g = 0; g < 4; ++g) {
                acc[g][r][0] = q[g * HID];
                acc[g][r][1] = q[g * HID + 1];
            }
        }
        for (int k = 0; k < LAT; k += 4) {
            float4 zr[TM];
#pragma unroll
            for (int r = 0; r < TM; ++r)
                zr[r] = *(const float4*)(z + (size_t)(m0 + ml0 + r) * LAT + k);
#pragma unroll
            for (int kk = 0; kk < 4; ++kk) {
                float w[4][TJ];
#pragma unroll
                for (int g = 0; g < 4; ++g)
#pragma unroll
                    for (int jj = 0; jj < TJ; ++jj)
                        w[g][jj] = W_init[(size_t)(g * HID + j0 + jj) * INIT_W + k + kk];
#pragma unroll
                for (int r = 0; r < TM; ++r) {
                    float hv = (kk == 0) ? zr[r].x : (kk == 1) ? zr[r].y
                             : (kk == 2) ? zr[r].z : zr[r].w;
#pragma unroll
                    for (int g = 0; g < 4; ++g) {
                        acc[g][r][0] = fmaf(hv, w[g][0], acc[g][r][0]);
                        acc[g][r][1] = fmaf(hv, w[g][1], acc[g][r][1]);
                    }
                }
            }
        }
#pragma unroll
        for (int r = 0; r < TM; ++r)
#pragma unroll
            for (int jj = 0; jj < TJ; ++jj) {
                int off = (ml0 + r) * HID + j0 + jj;
                sh_h0[off] = acc[0][r][jj];
                sh_c0[off] = acc[1][r][jj];
                sh_h1[off] = acc[2][r][jj];
                sh_c1[off] = acc[3][r][jj];
            }
    }
    __syncthreads();

    // ---- load WP (overwrites QI overlay): layout [v][q][cg][4] ----
    for (int i = tid; i < NVAR * GSZ; i += THREADS) {
        int v = i / GSZ, rem = i - v * GSZ;
        int q = rem >> 8, c = (rem >> 2) & 63, t = rem & 3;
        int g = q * 2 + (t >> 1), jj = t & 1;
        sh_Wp[i] = W_ih0[(g * HID + c * 2 + jj) * IH0_W + v];
    }
    __syncthreads();

    // ---- phase 2: time loop. ALL state accesses are row-group-local, so
    // only 64-thread named barriers are needed -> the 4 row-groups free-run
    // and hide each other's barrier drains and weight-load latency. ----
    for (int t = 0; t < T; ++t) {
        u64 acc[4][TM];

        // layer0 gates: init from P0[scenario], add prev (K=9), add h0@W_hh0^T
#pragma unroll
        for (int r = 0; r < TM; ++r) {
            int s = sh_scen[ml0 + r];
            const float* p = sh_P0 + s * GSZ + j0;
#pragma unroll
            for (int g = 0; g < 4; ++g)
                acc[g][r] = *(const u64*)(p + g * HID);
        }
#pragma unroll
        for (int v = 0; v < NVAR; ++v) {
            const float* wr = sh_Wp + (v << 9) + (cg << 2);
            longlong2 qa = *(const longlong2*)(wr);
            longlong2 qb = *(const longlong2*)(wr + 256);
            u64 w0 = (u64)qa.x, w1 = (u64)qa.y;
            u64 w2 = (u64)qb.x, w3 = (u64)qb.y;
#pragma unroll
            for (int r = 0; r < TM; ++r) {
                float pv = sh_prev[(ml0 + r) * 12 + v];
                u64 p2 = pack2(pv, pv);
                acc[0][r] = ffma2(p2, w0, acc[0][r]);
                acc[1][r] = ffma2(p2, w1, acc[1][r]);
                acc[2][r] = ffma2(p2, w2, acc[2][r]);
                acc[3][r] = ffma2(p2, w3, acc[3][r]);
            }
        }
        gemm128_2(acc, g_Wt0, sh_h0, ml0, cg);
        rg_bar(bid);                                  // S1: rg done reading h0

        // cell 0
#pragma unroll
        for (int r = 0; r < TM; ++r) {
            float i0, i1, f0, f1, g0, g1, o0, o1;
            unpack2(acc[0][r], i0, i1);
            unpack2(acc[1][r], f0, f1);
            unpack2(acc[2][r], g0, g1);
            unpack2(acc[3][r], o0, o1);
            int off = (ml0 + r) * HID + j0;
            float c0n = sigf(f0) * sh_c0[off]     + sigf(i0) * tanh_fast(g0);
            float c1n = sigf(f1) * sh_c0[off + 1] + sigf(i1) * tanh_fast(g1);
            sh_c0[off]     = c0n;
            sh_c0[off + 1] = c1n;
            sh_h0[off]     = sigf(o0) * tanh_fast(c0n);
            sh_h0[off + 1] = sigf(o1) * tanh_fast(c1n);
        }
        rg_bar(bid);                                  // S2: h0n visible in rg

        // layer1 gates: pre1 + h0n@W_ih1^T + h1@W_hh1^T
#pragma unroll
        for (int r = 0; r < TM; ++r)
#pragma unroll
            for (int g = 0; g < 4; ++g)
                acc[g][r] = *(const u64*)(sh_pre1 + g * HID + j0);
        gemm128_2(acc, g_Wt1, sh_h0, ml0, cg);
        gemm128_2(acc, g_Wt1 + HID * GSZ, sh_h1, ml0, cg);
        rg_bar(bid);                                  // S3: rg done reading h1

        // cell 1
#pragma unroll
        for (int r = 0; r < TM; ++r) {
            float i0, i1, f0, f1, g0, g1, o0, o1;
            unpack2(acc[0][r], i0, i1);
            unpack2(acc[1][r], f0, f1);
            unpack2(acc[2][r], g0, g1);
            unpack2(acc[3][r], o0, o1);
            int off = (ml0 + r) * HID + j0;
            float c0n = sigf(f0) * sh_c1[off]     + sigf(i0) * tanh_fast(g0);
            float c1n = sigf(f1) * sh_c1[off + 1] + sigf(i1) * tanh_fast(g1);
            sh_c1[off]     = c0n;
            sh_c1[off + 1] = c1n;
            sh_h1[off]     = sigf(o0) * tanh_fast(c0n);
            sh_h1[off + 1] = sigf(o1) * tanh_fast(c1n);
        }
        rg_bar(bid);                                  // S4: h1n visible in rg

        // output head (rg-local): rows ml0..ml0+7, 9 vars, 64 threads.
        // 4 independent FMA chains for ILP.
        for (int it = cg; it < TM * NVAR; it += 64) {
            int mr = it / NVAR, v = it - mr * NVAR;
            int m = ml0 + mr;
            const float* hrow = sh_h1 + m * HID;
            const float* wrow = sh_Wout + v * HID;
            float s0 = sh_bout[v], s1 = 0.f, s2 = 0.f, s3 = 0.f;
#pragma unroll 8
            for (int k = 0; k < HID; k += 4) {
                s0 = fmaf(hrow[k],     wrow[k],     s0);
                s1 = fmaf(hrow[k + 1], wrow[k + 1], s1);
                s2 = fmaf(hrow[k + 2], wrow[k + 2], s2);
                s3 = fmaf(hrow[k + 3], wrow[k + 3], s3);
            }
            float s = (s0 + s1) + (s2 + s3);
            sh_prev[m * 12 + v] = s;
            outp[((size_t)(m0 + m) * T + t) * NVAR + v] = s;
        }
        rg_bar(bid);                                  // S5: prev visible in rg
    }
}

extern "C" void kernel_launch(void* const* d_in, const int* in_sizes, int n_in,
                              void* d_out, int out_size) {
    // input order: z, scenario, [seq_length], emb, W_init, b_init, W_ih0, W_hh0,
    //              b_ih0, b_hh0, W_ih1, W_hh1, b_ih1, b_hh1, W_out, b_out
    int off = (n_in >= 16) ? 1 : 0;   // seq_length scalar present or not
    const float* z      = (const float*)d_in[0];
    const int*   scen   = (const int*)d_in[1];
    const float* emb    = (const float*)d_in[2 + off];
    const float* W_init = (const float*)d_in[3 + off];
    const float* b_init = (const float*)d_in[4 + off];
    const float* W_ih0  = (const float*)d_in[5 + off];
    const float* W_hh0  = (const float*)d_in[6 + off];
    const float* b_ih0  = (const float*)d_in[7 + off];
    const float* b_hh0  = (const float*)d_in[8 + off];
    const float* W_ih1  = (const float*)d_in[9 + off];
    const float* W_hh1  = (const float*)d_in[10 + off];
    const float* b_ih1  = (const float*)d_in[11 + off];
    const float* b_hh1  = (const float*)d_in[12 + off];
    const float* W_out  = (const float*)d_in[13 + off];
    const float* b_out  = (const float*)d_in[14 + off];
    float* outp = (float*)d_out;

    int B = in_sizes[0] / LAT;
    int T = out_size / (B * NVAR);

    cudaFuncSetAttribute(lstm_kernel,
                         cudaFuncAttributeMaxDynamicSharedMemorySize, SMEM_BYTES);

    transpose_kernel<<<(HID * GSZ + 255) / 256, 256>>>(W_hh0, W_ih1, W_hh1);
    lstm_kernel<<<B / M, THREADS, SMEM_BYTES>>>(
        z, scen, emb, W_init, b_init, W_ih0,
        b_ih0, b_hh0, b_ih1, b_hh1, W_out, b_out, outp, T);
}

// round 10
// speedup vs baseline: 1.0202x; 1.0195x over previous
#include <cuda_runtime.h>
#include <cuda_bf16.h>

#define LAT     32
#define HID     128
#define HSTR    132     // padded row stride (floats) -> 4 rsub rows hit banks {0,4,8,12}
#define GSZ     512     // 4*HID
#define NVAR    9
#define NSCEN   4
#define IH0_W   (NVAR + HID)   // 137
#define INIT_W  (LAT + HID)    // 160

#define M       32      // batch rows per CTA
#define THREADS 256
#define TM      8       // rows per thread (rows 4*r + rsub)
#define TJ      2       // hidden units per thread (one f32x2 pair)

typedef unsigned long long u64;

// -------- device scratch: weights relaid out [k][q][cg][4] --------
// per k-row (512 floats): q = gate-pair (0: gates0,1 ; 1: gates2,3)
//   float idx = k*512 + q*256 + cg*4 + g'*2 + jj   (g' = g&1)
__device__ __align__(16) float g_Wt0[HID * GSZ];        // W_hh0
__device__ __align__(16) float g_Wt1[2 * HID * GSZ];    // k<128: W_ih1, k>=128: W_hh1

__global__ void transpose_kernel(const float* __restrict__ W_hh0,
                                 const float* __restrict__ W_ih1,
                                 const float* __restrict__ W_hh1) {
    int i = blockIdx.x * blockDim.x + threadIdx.x;   // i = k*512 + col
    if (i >= HID * GSZ) return;
    int k = i >> 9, col = i & (GSZ - 1);
    int g = col >> 7, w = col & 127;
    int cg = w >> 1, jj = w & 1;
    int dst = (k << 9) + ((g >> 1) << 8) + (cg << 2) + ((g & 1) << 1) + jj;
    g_Wt0[dst]             = W_hh0[col * HID + k];
    g_Wt1[dst]             = W_ih1[col * HID + k];
    g_Wt1[HID * GSZ + dst] = W_hh1[col * HID + k];
}

__device__ __forceinline__ float sigf(float x) {
    return __fdividef(1.0f, 1.0f + __expf(-x));
}
__device__ __forceinline__ float tanh_fast(float x) {
    return __fdividef(2.0f, 1.0f + __expf(-2.0f * x)) - 1.0f;
}

// ---- packed fp32x2 helpers (sm_103a FFMA2 path) ----
__device__ __forceinline__ u64 pack2(float lo, float hi) {
    u64 d;
    asm("mov.b64 %0, {%1, %2};" : "=l"(d) : "f"(lo), "f"(hi));
    return d;
}
__device__ __forceinline__ void unpack2(u64 v, float& lo, float& hi) {
    asm("mov.b64 {%0, %1}, %2;" : "=f"(lo), "=f"(hi) : "l"(v));
}
__device__ __forceinline__ u64 ffma2(u64 a, u64 b, u64 c) {
    u64 d;
    asm("fma.rn.f32x2 %0, %1, %2, %3;" : "=l"(d) : "l"(a), "l"(b), "l"(c));
    return d;
}

// acc[g][r] (+)= shH[4r+rsub][k] * W[k][col-pair cg], K = 128, packed pairs.
// Warp covers 8 disjoint cgs x 4 rsubs -> each weight byte read ONCE per CTA.
__device__ __forceinline__ void gemm128_2(u64 acc[4][TM],
                                          const float* __restrict__ Wt,
                                          const float* __restrict__ shH,
                                          int rsub, int cg) {
    const float* wbase = Wt + (cg << 2);
    const float* hbase = shH + rsub * HSTR;
    for (int k = 0; k < HID; k += 4) {
        float4 h[TM];
#pragma unroll
        for (int r = 0; r < TM; ++r)
            h[r] = *(const float4*)(hbase + r * (4 * HSTR) + k);
#pragma unroll
        for (int kh = 0; kh < 4; kh += 2) {
            const float* w0p = wbase + ((k + kh) << 9);
            const float* w1p = wbase + ((k + kh + 1) << 9);
            longlong2 a0 = *(const longlong2*)(w0p);          // gates 0,1 @ kk
            longlong2 b0 = *(const longlong2*)(w0p + 256);    // gates 2,3 @ kk
            longlong2 a1 = *(const longlong2*)(w1p);          // gates 0,1 @ kk+1
            longlong2 b1 = *(const longlong2*)(w1p + 256);    // gates 2,3 @ kk+1
#pragma unroll
            for (int r = 0; r < TM; ++r) {
                float hv0 = (kh == 0) ? h[r].x : h[r].z;
                u64 h2 = pack2(hv0, hv0);
                acc[0][r] = ffma2(h2, (u64)a0.x, acc[0][r]);
                acc[1][r] = ffma2(h2, (u64)a0.y, acc[1][r]);
                acc[2][r] = ffma2(h2, (u64)b0.x, acc[2][r]);
                acc[3][r] = ffma2(h2, (u64)b0.y, acc[3][r]);
            }
#pragma unroll
            for (int r = 0; r < TM; ++r) {
                float hv1 = (kh == 0) ? h[r].y : h[r].w;
                u64 h2 = pack2(hv1, hv1);
                acc[0][r] = ffma2(h2, (u64)a1.x, acc[0][r]);
                acc[1][r] = ffma2(h2, (u64)a1.y, acc[1][r]);
                acc[2][r] = ffma2(h2, (u64)b1.x, acc[2][r]);
                acc[3][r] = ffma2(h2, (u64)b1.y, acc[3][r]);
            }
        }
    }
}

// SMEM layout (floats)
#define SM_H0    0
#define SM_H1    (SM_H0 + M * HSTR)
#define SM_C0    (SM_H1 + M * HSTR)
#define SM_C1    (SM_C0 + M * HSTR)
#define SM_PREV  (SM_C1 + M * HSTR)       // [M][12]
#define SM_P0    (SM_PREV + M * 12)       // [4][512]
#define SM_PRE1  (SM_P0 + NSCEN * GSZ)    // [512]
#define SM_WP    (SM_PRE1 + GSZ)          // [9][q][cg][4]; QI [4][512] overlaid (phase 1)
#define SM_WOUT  (SM_WP + NVAR * GSZ)     // [9][128]
#define SM_BOUT  (SM_WOUT + NVAR * HID)   // [16]
#define SM_SCEN  (SM_BOUT + 16)           // M ints
#define SM_FLAG  (SM_SCEN + M)
#define SM_FLOATS (SM_FLAG + 4)
#define SMEM_BYTES (SM_FLOATS * 4)

__global__ void __launch_bounds__(THREADS, 2)
lstm_kernel(const float* __restrict__ z, const int* __restrict__ scen_raw,
            const float* __restrict__ emb,
            const float* __restrict__ W_init, const float* __restrict__ b_init,
            const float* __restrict__ W_ih0,
            const float* __restrict__ b_ih0, const float* __restrict__ b_hh0,
            const float* __restrict__ b_ih1, const float* __restrict__ b_hh1,
            const float* __restrict__ W_out, const float* __restrict__ b_out,
            float* __restrict__ outp, int T) {
    extern __shared__ float sm[];
    float* sh_h0   = sm + SM_H0;
    float* sh_h1   = sm + SM_H1;
    float* sh_c0   = sm + SM_C0;
    float* sh_c1   = sm + SM_C1;
    float* sh_prev = sm + SM_PREV;
    float* sh_P0   = sm + SM_P0;
    float* sh_pre1 = sm + SM_PRE1;
    float* sh_Wp   = sm + SM_WP;      // phase 2
    float* sh_QI   = sm + SM_WP;      // phase 1 (overlay)
    float* sh_Wout = sm + SM_WOUT;
    float* sh_bout = sm + SM_BOUT;
    int*   sh_scen = (int*)(sm + SM_SCEN);
    int*   sh_flag = (int*)(sm + SM_FLAG);

    const int tid = threadIdx.x;
    const int m0  = blockIdx.x * M;

    // ---- scenario dtype detection (int64 vs int32): deterministic scan ----
    if (tid == 0) *sh_flag = 1;
    __syncthreads();
    {
        const unsigned* su = (const unsigned*)scen_raw;
        for (int k = tid; k < 512; k += THREADS)
            if (su[2 * k + 1] != 0u) *sh_flag = 0;
    }
    __syncthreads();
    const int is64 = *sh_flag;

    // ---- phase 0: tables into SMEM (QI overlaid on WP region) ----
    for (int m = tid; m < M; m += THREADS)
        sh_scen[m] = is64 ? scen_raw[2 * (m0 + m)] : scen_raw[m0 + m];
    for (int i = tid; i < NVAR * HID; i += THREADS) sh_Wout[i] = W_out[i];
    if (tid < NVAR) sh_bout[tid] = b_out[tid];
    for (int i = tid; i < GSZ; i += THREADS) sh_pre1[i] = b_ih1[i] + b_hh1[i];
    for (int i = tid; i < M * 12; i += THREADS) sh_prev[i] = 0.0f;
    for (int i = tid; i < NSCEN * GSZ; i += THREADS) {
        int s = i >> 9, j = i & (GSZ - 1);
        const float* e  = emb + s * HID;
        const float* w0 = W_ih0 + j * IH0_W + NVAR;
        const float* w1 = W_init + j * INIT_W + LAT;
        float v0 = b_ih0[j] + b_hh0[j];
        float v1 = b_init[j];
#pragma unroll 4
        for (int k = 0; k < HID; ++k) {
            float ek = e[k];
            v0 = fmaf(ek, w0[k], v0);
            v1 = fmaf(ek, w1[k], v1);
        }
        sh_P0[i] = v0;
        sh_QI[i] = v1;
    }
    __syncthreads();

    // lane mapping: warp covers 8 cgs x 4 rsubs
    const int lane   = tid & 31;
    const int warpid = tid >> 5;            // 0..7
    const int cgl    = lane & 7;
    const int rsub   = lane >> 3;           // 0..3
    const int cg     = warpid * 8 + cgl;    // 0..63
    const int j0     = cg * TJ;

    // thread's rows: 4*r + rsub, r = 0..7

    // ---- phase 1: h_init = z @ Wz^T + QI[scenario]  (slots: h0,c0,h1,c1) ----
    {
        float acc[4][TM][TJ];
#pragma unroll
        for (int r = 0; r < TM; ++r) {
            int s = sh_scen[4 * r + rsub];
            const float* q = sh_QI + s * GSZ + j0;
#pragma unroll
            for (int g = 0; g < 4; ++g) {
                acc[g][r][0] = q[g * HID];
                acc[g][r][1] = q[g * HID + 1];
            }
        }
        for (int k = 0; k < LAT; k += 4) {
            float4 zr[TM];
#pragma unroll
            for (int r = 0; r < TM; ++r)
                zr[r] = *(const float4*)(z + (size_t)(m0 + 4 * r + rsub) * LAT + k);
#pragma unroll
            for (int kk = 0; kk < 4; ++kk) {
                float w[4][TJ];
#pragma unroll
                for (int g = 0; g < 4; ++g)
#pragma unroll
                    for (int jj = 0; jj < TJ; ++jj)
                        w[g][jj] = W_init[(size_t)(g * HID + j0 + jj) * INIT_W + k + kk];
#pragma unroll
                for (int r = 0; r < TM; ++r) {
                    float hv = (kk == 0) ? zr[r].x : (kk == 1) ? zr[r].y
                             : (kk == 2) ? zr[r].z : zr[r].w;
#pragma unroll
                    for (int g = 0; g < 4; ++g) {
                        acc[g][r][0] = fmaf(hv, w[g][0], acc[g][r][0]);
                        acc[g][r][1] = fmaf(hv, w[g][1], acc[g][r][1]);
                    }
                }
            }
        }
#pragma unroll
        for (int r = 0; r < TM; ++r)
#pragma unroll
            for (int jj = 0; jj < TJ; ++jj) {
                int off = (4 * r + rsub) * HSTR + j0 + jj;
                sh_h0[off] = acc[0][r][jj];
                sh_c0[off] = acc[1][r][jj];
                sh_h1[off] = acc[2][r][jj];
                sh_c1[off] = acc[3][r][jj];
            }
    }
    __syncthreads();

    // ---- load WP (overwrites QI overlay): layout [v][q][cg][4] ----
    for (int i = tid; i < NVAR * GSZ; i += THREADS) {
        int v = i / GSZ, rem = i - v * GSZ;
        int q = rem >> 8, c = (rem >> 2) & 63, t = rem & 3;
        int g = q * 2 + (t >> 1), jj = t & 1;
        sh_Wp[i] = W_ih0[(g * HID + c * 2 + jj) * IH0_W + v];
    }
    __syncthreads();

    // ---- phase 2: time loop ----
    for (int t = 0; t < T; ++t) {
        u64 acc[4][TM];

        // layer0 gates: init from P0[scenario], add prev (K=9), add h0@W_hh0^T
#pragma unroll
        for (int r = 0; r < TM; ++r) {
            int s = sh_scen[4 * r + rsub];
            const float* p = sh_P0 + s * GSZ + j0;
#pragma unroll
            for (int g = 0; g < 4; ++g)
                acc[g][r] = *(const u64*)(p + g * HID);
        }
#pragma unroll
        for (int v = 0; v < NVAR; ++v) {
            const float* wr = sh_Wp + (v << 9) + (cg << 2);
            longlong2 qa = *(const longlong2*)(wr);
            longlong2 qb = *(const longlong2*)(wr + 256);
            u64 w0 = (u64)qa.x, w1 = (u64)qa.y;
            u64 w2 = (u64)qb.x, w3 = (u64)qb.y;
#pragma unroll
            for (int r = 0; r < TM; ++r) {
                float pv = sh_prev[(4 * r + rsub) * 12 + v];
                u64 p2 = pack2(pv, pv);
                acc[0][r] = ffma2(p2, w0, acc[0][r]);
                acc[1][r] = ffma2(p2, w1, acc[1][r]);
                acc[2][r] = ffma2(p2, w2, acc[2][r]);
                acc[3][r] = ffma2(p2, w3, acc[3][r]);
            }
        }
        gemm128_2(acc, g_Wt0, sh_h0, rsub, cg);
        __syncthreads();                              // S1: done reading h0

        // cell 0
#pragma unroll
        for (int r = 0; r < TM; ++r) {
            float i0, i1, f0, f1, g0, g1, o0, o1;
            unpack2(acc[0][r], i0, i1);
            unpack2(acc[1][r], f0, f1);
            unpack2(acc[2][r], g0, g1);
            unpack2(acc[3][r], o0, o1);
            int off = (4 * r + rsub) * HSTR + j0;
            float c0n = sigf(f0) * sh_c0[off]     + sigf(i0) * tanh_fast(g0);
            float c1n = sigf(f1) * sh_c0[off + 1] + sigf(i1) * tanh_fast(g1);
            sh_c0[off]     = c0n;
            sh_c0[off + 1] = c1n;
            sh_h0[off]     = sigf(o0) * tanh_fast(c0n);
            sh_h0[off + 1] = sigf(o1) * tanh_fast(c1n);
        }
        __syncthreads();                              // S2: h0n visible

        // layer1 gates: pre1 + h0n@W_ih1^T + h1@W_hh1^T
#pragma unroll
        for (int r = 0; r < TM; ++r)
#pragma unroll
            for (int g = 0; g < 4; ++g)
                acc[g][r] = *(const u64*)(sh_pre1 + g * HID + j0);
        gemm128_2(acc, g_Wt1, sh_h0, rsub, cg);
        gemm128_2(acc, g_Wt1 + HID * GSZ, sh_h1, rsub, cg);
        __syncthreads();                              // S3: done reading h1

        // cell 1
#pragma unroll
        for (int r = 0; r < TM; ++r) {
            float i0, i1, f0, f1, g0, g1, o0, o1;
            unpack2(acc[0][r], i0, i1);
            unpack2(acc[1][r], f0, f1);
            unpack2(acc[2][r], g0, g1);
            unpack2(acc[3][r], o0, o1);
            int off = (4 * r + rsub) * HSTR + j0;
            float c0n = sigf(f0) * sh_c1[off]     + sigf(i0) * tanh_fast(g0);
            float c1n = sigf(f1) * sh_c1[off + 1] + sigf(i1) * tanh_fast(g1);
            sh_c1[off]     = c0n;
            sh_c1[off + 1] = c1n;
            sh_h1[off]     = sigf(o0) * tanh_fast(c0n);
            sh_h1[off + 1] = sigf(o1) * tanh_fast(c1n);
        }
        __syncthreads();                              // S4: h1n visible

        // output head: out = h1n @ W_out^T + b_out ; also becomes prev
        for (int idx = tid; idx < M * NVAR; idx += THREADS) {
            int m = idx / NVAR, v = idx - m * NVAR;
            const float* hrow = sh_h1 + m * HSTR;
            const float* wrow = sh_Wout + v * HID;
            float s0 = sh_bout[v], s1 = 0.f, s2 = 0.f, s3 = 0.f;
#pragma unroll 8
            for (int k = 0; k < HID; k += 4) {
                s0 = fmaf(hrow[k],     wrow[k],     s0);
                s1 = fmaf(hrow[k + 1], wrow[k + 1], s1);
                s2 = fmaf(hrow[k + 2], wrow[k + 2], s2);
                s3 = fmaf(hrow[k + 3], wrow[k + 3], s3);
            }
            float s = (s0 + s1) + (s2 + s3);
            sh_prev[m * 12 + v] = s;
            outp[((size_t)(m0 + m) * T + t) * NVAR + v] = s;
        }
        __syncthreads();                              // S5: prev visible
    }
}

extern "C" void kernel_launch(void* const* d_in, const int* in_sizes, int n_in,
                              void* d_out, int out_size) {
    // input order: z, scenario, [seq_length], emb, W_init, b_init, W_ih0, W_hh0,
    //              b_ih0, b_hh0, W_ih1, W_hh1, b_ih1, b_hh1, W_out, b_out
    int off = (n_in >= 16) ? 1 : 0;   // seq_length scalar present or not
    const float* z      = (const float*)d_in[0];
    const int*   scen   = (const int*)d_in[1];
    const float* emb    = (const float*)d_in[2 + off];
    const float* W_init = (const float*)d_in[3 + off];
    const float* b_init = (const float*)d_in[4 + off];
    const float* W_ih0  = (const float*)d_in[5 + off];
    const float* W_hh0  = (const float*)d_in[6 + off];
    const float* b_ih0  = (const float*)d_in[7 + off];
    const float* b_hh0  = (const float*)d_in[8 + off];
    const float* W_ih1  = (const float*)d_in[9 + off];
    const float* W_hh1  = (const float*)d_in[10 + off];
    const float* b_ih1  = (const float*)d_in[11 + off];
    const float* b_hh1  = (const float*)d_in[12 + off];
    const float* W_out  = (const float*)d_in[13 + off];
    const float* b_out  = (const float*)d_in[14 + off];
    float* outp = (float*)d_out;

    int B = in_sizes[0] / LAT;
    int T = out_size / (B * NVAR);

    cudaFuncSetAttribute(lstm_kernel,
                         cudaFuncAttributeMaxDynamicSharedMemorySize, SMEM_BYTES);

    transpose_kernel<<<(HID * GSZ + 255) / 256, 256>>>(W_hh0, W_ih1, W_hh1);
    lstm_kernel<<<B / M, THREADS, SMEM_BYTES>>>(
        z, scen, emb, W_init, b_init, W_ih0,
        b_ih0, b_hh0, b_ih1, b_hh1, W_out, b_out, outp, T);
}